// round 16
// baseline (speedup 1.0000x reference)
#include <cuda_runtime.h>
#include <cuda_bf16.h>
#include <math_constants.h>
#include <cstdint>

// Problem constants
#define NROWS 8192
#define NCOLS 4096
#define EPSF 1e-12f

// GEMM tiling (bf16 operands, mma.sync m16n8k16), double-buffered.
// 4 warps (128 thr), 2m x 2n, 64x64 per warp -> min A/B re-read from SMEM.
#define BM 128
#define BN 128
#define BK 64                         // bf16 K elements per stage
#define NSTAGE (NROWS / BK)           // 128
#define AROW 72                       // padded row: 64 bf16 + 8 pad = 144 bytes
#define ATILE_B (BM * AROW * 2)       // 18432 bytes per operand tile
#define STAGE_B (2 * ATILE_B)         // 36864 bytes (A + B)
#define GEMM_SMEM (2 * STAGE_B)       // 73728 bytes (double buffer)

// ---------------------------------------------------------------------------
// Scratch (static device globals; no dynamic allocation allowed)
// ---------------------------------------------------------------------------
__device__ __nv_bfloat16  g_pxb[(size_t)NROWS * NCOLS];  // bf16 probs [n][c]
__device__ __nv_bfloat16  g_pyb[(size_t)NROWS * NCOLS];
__device__ __nv_bfloat16  g_pxt[(size_t)NROWS * NCOLS];  // bf16 transposed [c][n]
__device__ __nv_bfloat16  g_pyt[(size_t)NROWS * NCOLS];
__device__ float          g_rowent[NROWS];               // per-row entropy of X
__device__ float          g_lm[2][NCOLS];                // log(marg + eps)
__device__ double         g_mi;                          // MI accumulator

__device__ __forceinline__ uint32_t smem_u32(const void* p) {
    uint32_t a;
    asm("{ .reg .u64 t; cvta.to.shared.u64 t, %1; cvt.u32.u64 %0, t; }" : "=r"(a) : "l"(p));
    return a;
}

// ---------------------------------------------------------------------------
// Kernel 0: reset accumulators (graph is replayed; globals persist)
// ---------------------------------------------------------------------------
__global__ void init_kernel() { g_mi = 0.0; }

// ---------------------------------------------------------------------------
// Kernel 1: row softmax for X and Y, bf16 output, fused entropy for X.
// entropy_row = log(Z) - S/Z  with  Z = sum exp(x-m),  S = sum (x-m)exp(x-m)
// ---------------------------------------------------------------------------
__global__ __launch_bounds__(256) void softmax_kernel(const float* __restrict__ X,
                                                      const float* __restrict__ Y) {
    const int row  = blockIdx.x;
    const bool isX = row < NROWS;
    const int r    = isX ? row : row - NROWS;
    const float* __restrict__ src = (isX ? X : Y) + (size_t)r * NCOLS;
    __nv_bfloat16* __restrict__ dst = (isX ? g_pxb : g_pyb) + (size_t)r * NCOLS;

    const int tid = threadIdx.x;
    float4 v[4];
#pragma unroll
    for (int i = 0; i < 4; i++)
        v[i] = reinterpret_cast<const float4*>(src)[tid + i * 256];

    float m = -CUDART_INF_F;
#pragma unroll
    for (int i = 0; i < 4; i++)
        m = fmaxf(m, fmaxf(fmaxf(v[i].x, v[i].y), fmaxf(v[i].z, v[i].w)));
    __shared__ float sh_max[8];
#pragma unroll
    for (int o = 16; o > 0; o >>= 1) m = fmaxf(m, __shfl_xor_sync(0xffffffffu, m, o));
    if ((tid & 31) == 0) sh_max[tid >> 5] = m;
    __syncthreads();
    m = sh_max[0];
#pragma unroll
    for (int i = 1; i < 8; i++) m = fmaxf(m, sh_max[i]);
    __syncthreads();

    float z = 0.f, s = 0.f;
#pragma unroll
    for (int i = 0; i < 4; i++) {
        float t0 = v[i].x - m, t1 = v[i].y - m, t2 = v[i].z - m, t3 = v[i].w - m;
        float e0 = __expf(t0), e1 = __expf(t1), e2 = __expf(t2), e3 = __expf(t3);
        z += (e0 + e1) + (e2 + e3);
        s += (e0 * t0 + e1 * t1) + (e2 * t2 + e3 * t3);
        v[i].x = e0; v[i].y = e1; v[i].z = e2; v[i].w = e3;
    }
    __shared__ float sh_z[8], sh_s[8];
#pragma unroll
    for (int o = 16; o > 0; o >>= 1) {
        z += __shfl_xor_sync(0xffffffffu, z, o);
        s += __shfl_xor_sync(0xffffffffu, s, o);
    }
    if ((tid & 31) == 0) { sh_z[tid >> 5] = z; sh_s[tid >> 5] = s; }
    __syncthreads();
    z = 0.f; s = 0.f;
#pragma unroll
    for (int i = 0; i < 8; i++) { z += sh_z[i]; s += sh_s[i]; }

    const float invz = 1.0f / z;
#pragma unroll
    for (int i = 0; i < 4; i++) {
        __nv_bfloat162 p0 = __floats2bfloat162_rn(v[i].x * invz, v[i].y * invz);
        __nv_bfloat162 p1 = __floats2bfloat162_rn(v[i].z * invz, v[i].w * invz);
        uint2 pk;
        pk.x = *reinterpret_cast<uint32_t*>(&p0);
        pk.y = *reinterpret_cast<uint32_t*>(&p1);
        reinterpret_cast<uint2*>(dst)[tid + i * 256] = pk;
    }
    if (isX && tid == 0)
        g_rowent[r] = logf(z) - s * invz;
}

// ---------------------------------------------------------------------------
// Kernel 1b: bf16 tiled transpose [n][c] -> [c][n], 64x64 tiles.
// ---------------------------------------------------------------------------
__global__ __launch_bounds__(256) void transpose_kernel() {
    __shared__ __nv_bfloat16 t[64][65];
    const int mat = blockIdx.z;
    const __nv_bfloat16* __restrict__ src = mat ? g_pyb : g_pxb;
    __nv_bfloat16* __restrict__ dst       = mat ? g_pyt : g_pxt;
    const int c0 = blockIdx.x * 64;
    const int r0 = blockIdx.y * 64;
    const int tid = threadIdx.x;

#pragma unroll
    for (int i = 0; i < 2; i++) {
        const int lin = tid + i * 256;       // 0..511
        const int row = lin >> 3;            // n-row 0..63
        const int q   = lin & 7;             // 16B chunk 0..7
        uint4 v = *reinterpret_cast<const uint4*>(
            &src[(size_t)(r0 + row) * NCOLS + c0 + q * 8]);
        const __nv_bfloat16* e = reinterpret_cast<const __nv_bfloat16*>(&v);
#pragma unroll
        for (int j = 0; j < 8; j++) t[row][q * 8 + j] = e[j];
    }
    __syncthreads();
#pragma unroll
    for (int i = 0; i < 2; i++) {
        const int lin = tid + i * 256;
        const int cw = lin >> 3;             // c-row 0..63
        const int nq = lin & 7;              // 8-sample group 0..7
        __nv_bfloat16 o[8];
#pragma unroll
        for (int j = 0; j < 8; j++) o[j] = t[nq * 8 + j][cw];
        *reinterpret_cast<uint4*>(&dst[(size_t)(c0 + cw) * NROWS + r0 + nq * 8]) =
            *reinterpret_cast<uint4*>(o);
    }
}

// ---------------------------------------------------------------------------
// Kernel 2: fused marginal + log from transposed bf16 (contiguous row sums).
// ---------------------------------------------------------------------------
__global__ __launch_bounds__(256) void marglog_kernel() {
    const int wid  = threadIdx.x >> 5;
    const int lane = threadIdx.x & 31;
    const int row  = blockIdx.x * 8 + wid;
    const int arr  = blockIdx.y;
    const __nv_bfloat16* __restrict__ p = (arr ? g_pyt : g_pxt) + (size_t)row * NROWS;

    float sum = 0.f;
#pragma unroll 4
    for (int it = 0; it < 32; it++) {
        uint4 v = reinterpret_cast<const uint4*>(p)[lane + it * 32];
        const __nv_bfloat162* h = reinterpret_cast<const __nv_bfloat162*>(&v);
#pragma unroll
        for (int j = 0; j < 4; j++) {
            float2 f = __bfloat1622float2(h[j]);
            sum += f.x + f.y;
        }
    }
#pragma unroll
    for (int o = 16; o > 0; o >>= 1) sum += __shfl_xor_sync(0xffffffffu, sum, o);
    if (lane == 0)
        g_lm[arr][row] = logf(sum * (1.0f / NROWS) + EPSF);
}

// ---------------------------------------------------------------------------
// Kernel 3: bf16 GEMM joint = pxt * pyt^T / N via mma.sync.m16n8k16 (HMMA).
// 4 warps, 2m x 2n, 64x64 warp tile -> A and B each re-read only 2x from
// SMEM (vs 4x/2x before). B uses ldmatrix.x4 (2 n-frags + 2 k-halves).
// Double-buffered SMEM, one __syncthreads per stage, fused MI epilogue.
// ---------------------------------------------------------------------------
__global__ __launch_bounds__(128, 2) void gemm_mi_kernel() {
    extern __shared__ __align__(16) char sm_raw[];

    const int tid  = threadIdx.x;
    const int wid  = tid >> 5;
    const int lane = tid & 31;

    // grouped rasterization: 8 m-tiles per group for L2 reuse
    const int pid = blockIdx.x;
    const int pm  = ((pid >> 8) << 3) + (pid & 7);
    const int pn  = (pid & 255) >> 3;
    const int bm = pm * BM, bn = pn * BN;
    const float invn = 1.0f / NROWS;

    // ---- load slots: 8 x 16B chunks per operand per thread (1024 chunks) ----
    const __nv_bfloat16* srcA[8]; const __nv_bfloat16* srcB[8];
    int dstOff[8];
#pragma unroll
    for (int i = 0; i < 8; i++) {
        const int c = tid + i * 128;        // 0..1023
        const int row = c >> 3, q = c & 7;  // tile row, 16B chunk in row
        dstOff[i] = row * AROW + q * 8;     // bf16 elements
        srcA[i] = g_pxt + (size_t)(bm + row) * NROWS + q * 8;
        srcB[i] = g_pyt + (size_t)(bn + row) * NROWS + q * 8;
    }

    // ---- ldmatrix lane addressing (relative offsets within a stage buffer) ----
    const int wm = wid & 1;                 // m half (64)
    const int wn = wid >> 1;                // n half (64)
    const uint32_t sm_b = smem_u32(sm_raw);
    const int r8   = lane & 7;
    const int quad = lane >> 3;             // 4 lane-groups of 8
    // A x4: quadrant: (m+0/+8) x (k0/k8)
    uint32_t a_off[4];
#pragma unroll
    for (int mf = 0; mf < 4; mf++)
        a_off[mf] = (uint32_t)(((wm * 64 + mf * 16) + (quad & 1) * 8 + r8) * (AROW * 2)
                               + (quad >> 1) * 16);
    // B x4: 4 matrices = (n-lo,k0),(n-lo,k8),(n-hi,k0),(n-hi,k8) per nf-pair
    uint32_t b_off[4];
#pragma unroll
    for (int nfp = 0; nfp < 4; nfp++)
        b_off[nfp] = (uint32_t)(ATILE_B
                     + ((wn * 64 + nfp * 16) + (quad >> 1) * 8 + r8) * (AROW * 2)
                     + (quad & 1) * 16);

    float acc[4][8][4];
#pragma unroll
    for (int i = 0; i < 4; i++)
#pragma unroll
        for (int j = 0; j < 8; j++)
#pragma unroll
            for (int k = 0; k < 4; k++) acc[i][j][k] = 0.f;

    // preload stage 0 and store into buffer 0
    uint4 ra[8], rb[8];
#pragma unroll
    for (int i = 0; i < 8; i++) {
        ra[i] = *reinterpret_cast<const uint4*>(srcA[i]);
        rb[i] = *reinterpret_cast<const uint4*>(srcB[i]);
    }
#pragma unroll
    for (int i = 0; i < 8; i++) {
        *reinterpret_cast<uint4*>(sm_raw + dstOff[i] * 2)           = ra[i];
        *reinterpret_cast<uint4*>(sm_raw + ATILE_B + dstOff[i] * 2) = rb[i];
    }
    __syncthreads();

    for (int s = 0; s < NSTAGE; s++) {
        const uint32_t bufb = sm_b + (uint32_t)((s & 1) * STAGE_B);

        // prefetch stage s+1 (LDG latency hidden under the MMA work below)
        if (s + 1 < NSTAGE) {
#pragma unroll
            for (int i = 0; i < 8; i++) {
                ra[i] = *reinterpret_cast<const uint4*>(srcA[i] + (size_t)(s + 1) * BK);
                rb[i] = *reinterpret_cast<const uint4*>(srcB[i] + (size_t)(s + 1) * BK);
            }
        }

#pragma unroll
        for (int ks = 0; ks < 4; ks++) {            // four k16 steps (byte offset +32)
            const uint32_t ko = ks * 32;
            uint32_t a[4][4], b[4][4];
#pragma unroll
            for (int mf = 0; mf < 4; mf++)
                asm volatile("ldmatrix.sync.aligned.m8n8.x4.shared.b16 {%0,%1,%2,%3}, [%4];"
                    : "=r"(a[mf][0]), "=r"(a[mf][1]), "=r"(a[mf][2]), "=r"(a[mf][3])
                    : "r"(bufb + a_off[mf] + ko));
#pragma unroll
            for (int nfp = 0; nfp < 4; nfp++)
                asm volatile("ldmatrix.sync.aligned.m8n8.x4.shared.b16 {%0,%1,%2,%3}, [%4];"
                    : "=r"(b[nfp][0]), "=r"(b[nfp][1]), "=r"(b[nfp][2]), "=r"(b[nfp][3])
                    : "r"(bufb + b_off[nfp] + ko));
#pragma unroll
            for (int mf = 0; mf < 4; mf++)
#pragma unroll
                for (int nf = 0; nf < 8; nf++) {
                    const int nfp = nf >> 1, h = (nf & 1) * 2;
                    asm volatile("mma.sync.aligned.m16n8k16.row.col.f32.bf16.bf16.f32 "
                        "{%0,%1,%2,%3}, {%4,%5,%6,%7}, {%8,%9}, {%0,%1,%2,%3};"
                        : "+f"(acc[mf][nf][0]), "+f"(acc[mf][nf][1]),
                          "+f"(acc[mf][nf][2]), "+f"(acc[mf][nf][3])
                        : "r"(a[mf][0]), "r"(a[mf][1]), "r"(a[mf][2]), "r"(a[mf][3]),
                          "r"(b[nfp][h]), "r"(b[nfp][h + 1]));
                }
        }

        // store stage s+1 into the other buffer (no reader until next sync)
        if (s + 1 < NSTAGE) {
            char* nb = sm_raw + ((s + 1) & 1) * STAGE_B;
#pragma unroll
            for (int i = 0; i < 8; i++) {
                *reinterpret_cast<uint4*>(nb + dstOff[i] * 2)           = ra[i];
                *reinterpret_cast<uint4*>(nb + ATILE_B + dstOff[i] * 2) = rb[i];
            }
        }
        __syncthreads();
    }

    // ---- fused MI epilogue ----
    // acc[mf][nf]: c0: (row=lane>>2, col=(lane&3)*2), c1: col+1, c2: row+8, c3: row+8,col+1
    const int mrow = lane >> 2;
    const int ncol = (lane & 3) * 2;
    double lsum = 0.0;
#pragma unroll
    for (int mf = 0; mf < 4; mf++) {
        const int m0 = bm + wm * 64 + mf * 16 + mrow;
        const float lmx0 = g_lm[0][m0];
        const float lmx1 = g_lm[0][m0 + 8];
#pragma unroll
        for (int nf = 0; nf < 8; nf++) {
            const int n0 = bn + wn * 64 + nf * 8 + ncol;
            const float lmy0 = g_lm[1][n0];
            const float lmy1 = g_lm[1][n0 + 1];
            const float j0 = acc[mf][nf][0] * invn;
            const float j1 = acc[mf][nf][1] * invn;
            const float j2 = acc[mf][nf][2] * invn;
            const float j3 = acc[mf][nf][3] * invn;
            lsum += (double)(j0 * (__logf(j0 + EPSF) - lmx0 - lmy0));
            lsum += (double)(j1 * (__logf(j1 + EPSF) - lmx0 - lmy1));
            lsum += (double)(j2 * (__logf(j2 + EPSF) - lmx1 - lmy0));
            lsum += (double)(j3 * (__logf(j3 + EPSF) - lmx1 - lmy1));
        }
    }

    __syncthreads();
    double* red = reinterpret_cast<double*>(sm_raw);
    red[tid] = lsum;
    __syncthreads();
#pragma unroll
    for (int o = 64; o > 0; o >>= 1) {
        if (tid < o) red[tid] += red[tid + o];
        __syncthreads();
    }
    if (tid == 0) atomicAdd(&g_mi, red[0]);
}

// ---------------------------------------------------------------------------
// Kernel 4: finalize — deterministic row-entropy reduction + output
// ---------------------------------------------------------------------------
__global__ __launch_bounds__(256) void finalize_kernel(float* __restrict__ out) {
    __shared__ float red[256];
    const int tid = threadIdx.x;
    float s = 0.f;
    for (int i = tid; i < NROWS; i += 256) s += g_rowent[i];
    red[tid] = s;
    __syncthreads();
#pragma unroll
    for (int o = 128; o > 0; o >>= 1) {
        if (tid < o) red[tid] += red[tid + o];
        __syncthreads();
    }
    if (tid == 0) {
        out[0] = red[0] * (1.0f / NROWS);
        out[1] = (float)g_mi;
    }
}

// ---------------------------------------------------------------------------
extern "C" void kernel_launch(void* const* d_in, const int* in_sizes, int n_in,
                              void* d_out, int out_size) {
    const float* X = (const float*)d_in[0];
    const float* Y = (const float*)d_in[1];
    float* out = (float*)d_out;

    cudaFuncSetAttribute(gemm_mi_kernel,
                         cudaFuncAttributeMaxDynamicSharedMemorySize, GEMM_SMEM);

    init_kernel<<<1, 1>>>();
    softmax_kernel<<<2 * NROWS, 256>>>(X, Y);
    transpose_kernel<<<dim3(NCOLS / 64, NROWS / 64, 2), 256>>>();
    marglog_kernel<<<dim3(NCOLS / 8, 2), 256>>>();
    gemm_mi_kernel<<<(NCOLS / BM) * (NCOLS / BN), 128, GEMM_SMEM>>>();
    finalize_kernel<<<1, 256>>>(out);
}

// round 17
// speedup vs baseline: 1.4892x; 1.4892x over previous
#include <cuda_runtime.h>
#include <cuda_bf16.h>
#include <math_constants.h>
#include <cstdint>

// Problem constants
#define NROWS 8192
#define NCOLS 4096
#define EPSF 1e-12f

// GEMM tiling (bf16 operands, mma.sync m16n8k16), double-buffered, cp.async
#define BM 128
#define BN 128
#define BK 64                         // bf16 K elements per stage
#define NSTAGE (NROWS / BK)           // 128
#define AROW 72                       // padded row: 64 bf16 + 8 pad = 144 bytes
#define ATILE_B (BM * AROW * 2)       // 18432 bytes per operand tile
#define STAGE_B (2 * ATILE_B)         // 36864 bytes (A + B)
#define GEMM_SMEM (2 * STAGE_B)       // 73728 bytes (double buffer)

// ---------------------------------------------------------------------------
// Scratch (static device globals; no dynamic allocation allowed)
// ---------------------------------------------------------------------------
__device__ __nv_bfloat16  g_pxb[(size_t)NROWS * NCOLS];  // bf16 probs [n][c]
__device__ __nv_bfloat16  g_pyb[(size_t)NROWS * NCOLS];
__device__ __nv_bfloat16  g_pxt[(size_t)NROWS * NCOLS];  // bf16 transposed [c][n]
__device__ __nv_bfloat16  g_pyt[(size_t)NROWS * NCOLS];
__device__ float          g_rowent[NROWS];               // per-row entropy of X
__device__ float          g_lm[2][NCOLS];                // log(marg + eps)
__device__ double         g_mi;                          // MI accumulator

__device__ __forceinline__ uint32_t smem_u32(const void* p) {
    uint32_t a;
    asm("{ .reg .u64 t; cvta.to.shared.u64 t, %1; cvt.u32.u64 %0, t; }" : "=r"(a) : "l"(p));
    return a;
}
__device__ __forceinline__ void cp_async16(uint32_t smem_addr, const void* gptr) {
    asm volatile("cp.async.cg.shared.global [%0], [%1], 16;" :: "r"(smem_addr), "l"(gptr) : "memory");
}
#define CP_COMMIT() asm volatile("cp.async.commit_group;" ::: "memory")
#define CP_WAIT0()  asm volatile("cp.async.wait_group 0;" ::: "memory")

// ---------------------------------------------------------------------------
// Kernel 0: reset accumulators (graph is replayed; globals persist)
// ---------------------------------------------------------------------------
__global__ void init_kernel() { g_mi = 0.0; }

// ---------------------------------------------------------------------------
// Kernel 1: row softmax for X and Y, bf16 output, fused entropy for X.
// entropy_row = log(Z) - S/Z  with  Z = sum exp(x-m),  S = sum (x-m)exp(x-m)
// ---------------------------------------------------------------------------
__global__ __launch_bounds__(256) void softmax_kernel(const float* __restrict__ X,
                                                      const float* __restrict__ Y) {
    const int row  = blockIdx.x;
    const bool isX = row < NROWS;
    const int r    = isX ? row : row - NROWS;
    const float* __restrict__ src = (isX ? X : Y) + (size_t)r * NCOLS;
    __nv_bfloat16* __restrict__ dst = (isX ? g_pxb : g_pyb) + (size_t)r * NCOLS;

    const int tid = threadIdx.x;
    float4 v[4];
#pragma unroll
    for (int i = 0; i < 4; i++)
        v[i] = reinterpret_cast<const float4*>(src)[tid + i * 256];

    float m = -CUDART_INF_F;
#pragma unroll
    for (int i = 0; i < 4; i++)
        m = fmaxf(m, fmaxf(fmaxf(v[i].x, v[i].y), fmaxf(v[i].z, v[i].w)));
    __shared__ float sh_max[8];
#pragma unroll
    for (int o = 16; o > 0; o >>= 1) m = fmaxf(m, __shfl_xor_sync(0xffffffffu, m, o));
    if ((tid & 31) == 0) sh_max[tid >> 5] = m;
    __syncthreads();
    m = sh_max[0];
#pragma unroll
    for (int i = 1; i < 8; i++) m = fmaxf(m, sh_max[i]);
    __syncthreads();

    float z = 0.f, s = 0.f;
#pragma unroll
    for (int i = 0; i < 4; i++) {
        float t0 = v[i].x - m, t1 = v[i].y - m, t2 = v[i].z - m, t3 = v[i].w - m;
        float e0 = __expf(t0), e1 = __expf(t1), e2 = __expf(t2), e3 = __expf(t3);
        z += (e0 + e1) + (e2 + e3);
        s += (e0 * t0 + e1 * t1) + (e2 * t2 + e3 * t3);
        v[i].x = e0; v[i].y = e1; v[i].z = e2; v[i].w = e3;
    }
    __shared__ float sh_z[8], sh_s[8];
#pragma unroll
    for (int o = 16; o > 0; o >>= 1) {
        z += __shfl_xor_sync(0xffffffffu, z, o);
        s += __shfl_xor_sync(0xffffffffu, s, o);
    }
    if ((tid & 31) == 0) { sh_z[tid >> 5] = z; sh_s[tid >> 5] = s; }
    __syncthreads();
    z = 0.f; s = 0.f;
#pragma unroll
    for (int i = 0; i < 8; i++) { z += sh_z[i]; s += sh_s[i]; }

    const float invz = 1.0f / z;
#pragma unroll
    for (int i = 0; i < 4; i++) {
        __nv_bfloat162 p0 = __floats2bfloat162_rn(v[i].x * invz, v[i].y * invz);
        __nv_bfloat162 p1 = __floats2bfloat162_rn(v[i].z * invz, v[i].w * invz);
        uint2 pk;
        pk.x = *reinterpret_cast<uint32_t*>(&p0);
        pk.y = *reinterpret_cast<uint32_t*>(&p1);
        reinterpret_cast<uint2*>(dst)[tid + i * 256] = pk;
    }
    if (isX && tid == 0)
        g_rowent[r] = logf(z) - s * invz;
}

// ---------------------------------------------------------------------------
// Kernel 1b: bf16 tiled transpose [n][c] -> [c][n], 64x64 tiles.
// ---------------------------------------------------------------------------
__global__ __launch_bounds__(256) void transpose_kernel() {
    __shared__ __nv_bfloat16 t[64][65];
    const int mat = blockIdx.z;
    const __nv_bfloat16* __restrict__ src = mat ? g_pyb : g_pxb;
    __nv_bfloat16* __restrict__ dst       = mat ? g_pyt : g_pxt;
    const int c0 = blockIdx.x * 64;
    const int r0 = blockIdx.y * 64;
    const int tid = threadIdx.x;

#pragma unroll
    for (int i = 0; i < 2; i++) {
        const int lin = tid + i * 256;       // 0..511
        const int row = lin >> 3;            // n-row 0..63
        const int q   = lin & 7;             // 16B chunk 0..7
        uint4 v = *reinterpret_cast<const uint4*>(
            &src[(size_t)(r0 + row) * NCOLS + c0 + q * 8]);
        const __nv_bfloat16* e = reinterpret_cast<const __nv_bfloat16*>(&v);
#pragma unroll
        for (int j = 0; j < 8; j++) t[row][q * 8 + j] = e[j];
    }
    __syncthreads();
#pragma unroll
    for (int i = 0; i < 2; i++) {
        const int lin = tid + i * 256;
        const int cw = lin >> 3;             // c-row 0..63
        const int nq = lin & 7;              // 8-sample group 0..7
        __nv_bfloat16 o[8];
#pragma unroll
        for (int j = 0; j < 8; j++) o[j] = t[nq * 8 + j][cw];
        *reinterpret_cast<uint4*>(&dst[(size_t)(c0 + cw) * NROWS + r0 + nq * 8]) =
            *reinterpret_cast<uint4*>(o);
    }
}

// ---------------------------------------------------------------------------
// Kernel 2: fused marginal + log from transposed bf16 (contiguous row sums).
// ---------------------------------------------------------------------------
__global__ __launch_bounds__(256) void marglog_kernel() {
    const int wid  = threadIdx.x >> 5;
    const int lane = threadIdx.x & 31;
    const int row  = blockIdx.x * 8 + wid;
    const int arr  = blockIdx.y;
    const __nv_bfloat16* __restrict__ p = (arr ? g_pyt : g_pxt) + (size_t)row * NROWS;

    float sum = 0.f;
#pragma unroll 4
    for (int it = 0; it < 32; it++) {
        uint4 v = reinterpret_cast<const uint4*>(p)[lane + it * 32];
        const __nv_bfloat162* h = reinterpret_cast<const __nv_bfloat162*>(&v);
#pragma unroll
        for (int j = 0; j < 4; j++) {
            float2 f = __bfloat1622float2(h[j]);
            sum += f.x + f.y;
        }
    }
#pragma unroll
    for (int o = 16; o > 0; o >>= 1) sum += __shfl_xor_sync(0xffffffffu, sum, o);
    if (lane == 0)
        g_lm[arr][row] = logf(sum * (1.0f / NROWS) + EPSF);
}

// ---------------------------------------------------------------------------
// Kernel 3: bf16 GEMM joint = pxt * pyt^T / N via mma.sync.m16n8k16 (HMMA).
// 8 warps (2m x 4n, 64x32 per warp), double-buffered SMEM fed by cp.async:
// per stage: wait_group 0 -> __syncthreads -> issue cp.async(s+1) -> compute.
// Fused MI epilogue.
// ---------------------------------------------------------------------------
__global__ __launch_bounds__(256, 2) void gemm_mi_kernel() {
    extern __shared__ __align__(16) char sm_raw[];

    const int tid  = threadIdx.x;
    const int wid  = tid >> 5;
    const int lane = tid & 31;

    // grouped rasterization: 8 m-tiles per group for L2 reuse
    const int pid = blockIdx.x;
    const int pm  = ((pid >> 8) << 3) + (pid & 7);
    const int pn  = (pid & 255) >> 3;
    const int bm = pm * BM, bn = pn * BN;
    const float invn = 1.0f / NROWS;

    // ---- load slots: 4 x 16B chunks per operand per thread (1024 chunks) ----
    const __nv_bfloat16* srcA[4]; const __nv_bfloat16* srcB[4];
    uint32_t dstOff[4];                      // byte offsets within a stage buffer
#pragma unroll
    for (int i = 0; i < 4; i++) {
        const int c = tid + i * 256;        // 0..1023
        const int row = c >> 3, q = c & 7;  // tile row, 16B chunk in row
        dstOff[i] = (uint32_t)(row * AROW * 2 + q * 16);
        srcA[i] = g_pxt + (size_t)(bm + row) * NROWS + q * 8;
        srcB[i] = g_pyt + (size_t)(bn + row) * NROWS + q * 8;
    }

    // ---- ldmatrix lane addressing (relative offsets within a stage buffer) ----
    const int wm = wid & 1;                 // m half (64)
    const int wn = wid >> 1;                // n quarter (32)
    const uint32_t sm_b = smem_u32(sm_raw);
    const int r8   = lane & 7;
    const int quad = lane >> 3;             // A x4: quadrant 0..3
    uint32_t a_off[4], b_off[4];
#pragma unroll
    for (int mf = 0; mf < 4; mf++)
        a_off[mf] = (uint32_t)(((wm * 64 + mf * 16) + (quad & 1) * 8 + r8) * (AROW * 2)
                               + (quad >> 1) * 16);
    const int bhalf = (lane >> 3) & 1;      // B x2: k halves
#pragma unroll
    for (int nf = 0; nf < 4; nf++)
        b_off[nf] = (uint32_t)(ATILE_B + ((wn * 32 + nf * 8) + r8) * (AROW * 2) + bhalf * 16);

    float acc[4][4][4];
#pragma unroll
    for (int i = 0; i < 4; i++)
#pragma unroll
        for (int j = 0; j < 4; j++)
#pragma unroll
            for (int k = 0; k < 4; k++) acc[i][j][k] = 0.f;

    // prologue: cp.async stage 0 into buffer 0
#pragma unroll
    for (int i = 0; i < 4; i++) {
        cp_async16(sm_b + dstOff[i],           srcA[i]);
        cp_async16(sm_b + ATILE_B + dstOff[i], srcB[i]);
    }
    CP_COMMIT();

    for (int s = 0; s < NSTAGE; s++) {
        const uint32_t bufb = sm_b + (uint32_t)((s & 1) * STAGE_B);

        CP_WAIT0();                           // stage s resident in buffer s&1
        __syncthreads();                      // visible to all; all done reading other buf

        // issue stage s+1 into the other buffer (streams during compute)
        if (s + 1 < NSTAGE) {
            const uint32_t nb = sm_b + (uint32_t)(((s + 1) & 1) * STAGE_B);
#pragma unroll
            for (int i = 0; i < 4; i++) {
                cp_async16(nb + dstOff[i],           srcA[i] + (size_t)(s + 1) * BK);
                cp_async16(nb + ATILE_B + dstOff[i], srcB[i] + (size_t)(s + 1) * BK);
            }
            CP_COMMIT();
        }

#pragma unroll
        for (int ks = 0; ks < 4; ks++) {            // four k16 steps (byte offset +32)
            const uint32_t ko = ks * 32;
            uint32_t a[4][4], b[4][2];
#pragma unroll
            for (int mf = 0; mf < 4; mf++)
                asm volatile("ldmatrix.sync.aligned.m8n8.x4.shared.b16 {%0,%1,%2,%3}, [%4];"
                    : "=r"(a[mf][0]), "=r"(a[mf][1]), "=r"(a[mf][2]), "=r"(a[mf][3])
                    : "r"(bufb + a_off[mf] + ko));
#pragma unroll
            for (int nf = 0; nf < 4; nf++)
                asm volatile("ldmatrix.sync.aligned.m8n8.x2.shared.b16 {%0,%1}, [%2];"
                    : "=r"(b[nf][0]), "=r"(b[nf][1])
                    : "r"(bufb + b_off[nf] + ko));
#pragma unroll
            for (int mf = 0; mf < 4; mf++)
#pragma unroll
                for (int nf = 0; nf < 4; nf++)
                    asm volatile("mma.sync.aligned.m16n8k16.row.col.f32.bf16.bf16.f32 "
                        "{%0,%1,%2,%3}, {%4,%5,%6,%7}, {%8,%9}, {%0,%1,%2,%3};"
                        : "+f"(acc[mf][nf][0]), "+f"(acc[mf][nf][1]),
                          "+f"(acc[mf][nf][2]), "+f"(acc[mf][nf][3])
                        : "r"(a[mf][0]), "r"(a[mf][1]), "r"(a[mf][2]), "r"(a[mf][3]),
                          "r"(b[nf][0]), "r"(b[nf][1]));
        }
    }

    // ---- fused MI epilogue ----
    // acc[mf][nf]: c0: (row=lane>>2, col=(lane&3)*2), c1: col+1, c2: row+8, c3: row+8,col+1
    const int mrow = lane >> 2;
    const int ncol = (lane & 3) * 2;
    double lsum = 0.0;
#pragma unroll
    for (int mf = 0; mf < 4; mf++) {
        const int m0 = bm + wm * 64 + mf * 16 + mrow;
        const float lmx0 = g_lm[0][m0];
        const float lmx1 = g_lm[0][m0 + 8];
#pragma unroll
        for (int nf = 0; nf < 4; nf++) {
            const int n0 = bn + wn * 32 + nf * 8 + ncol;
            const float lmy0 = g_lm[1][n0];
            const float lmy1 = g_lm[1][n0 + 1];
            const float j0 = acc[mf][nf][0] * invn;
            const float j1 = acc[mf][nf][1] * invn;
            const float j2 = acc[mf][nf][2] * invn;
            const float j3 = acc[mf][nf][3] * invn;
            lsum += (double)(j0 * (__logf(j0 + EPSF) - lmx0 - lmy0));
            lsum += (double)(j1 * (__logf(j1 + EPSF) - lmx0 - lmy1));
            lsum += (double)(j2 * (__logf(j2 + EPSF) - lmx1 - lmy0));
            lsum += (double)(j3 * (__logf(j3 + EPSF) - lmx1 - lmy1));
        }
    }

    __syncthreads();
    double* red = reinterpret_cast<double*>(sm_raw);
    red[tid] = lsum;
    __syncthreads();
#pragma unroll
    for (int o = 128; o > 0; o >>= 1) {
        if (tid < o) red[tid] += red[tid + o];
        __syncthreads();
    }
    if (tid == 0) atomicAdd(&g_mi, red[0]);
}

// ---------------------------------------------------------------------------
// Kernel 4: finalize — deterministic row-entropy reduction + output
// ---------------------------------------------------------------------------
__global__ __launch_bounds__(256) void finalize_kernel(float* __restrict__ out) {
    __shared__ float red[256];
    const int tid = threadIdx.x;
    float s = 0.f;
    for (int i = tid; i < NROWS; i += 256) s += g_rowent[i];
    red[tid] = s;
    __syncthreads();
#pragma unroll
    for (int o = 128; o > 0; o >>= 1) {
        if (tid < o) red[tid] += red[tid + o];
        __syncthreads();
    }
    if (tid == 0) {
        out[0] = red[0] * (1.0f / NROWS);
        out[1] = (float)g_mi;
    }
}

// ---------------------------------------------------------------------------
extern "C" void kernel_launch(void* const* d_in, const int* in_sizes, int n_in,
                              void* d_out, int out_size) {
    const float* X = (const float*)d_in[0];
    const float* Y = (const float*)d_in[1];
    float* out = (float*)d_out;

    cudaFuncSetAttribute(gemm_mi_kernel,
                         cudaFuncAttributeMaxDynamicSharedMemorySize, GEMM_SMEM);

    init_kernel<<<1, 1>>>();
    softmax_kernel<<<2 * NROWS, 256>>>(X, Y);
    transpose_kernel<<<dim3(NCOLS / 64, NROWS / 64, 2), 256>>>();
    marglog_kernel<<<dim3(NCOLS / 8, 2), 256>>>();
    gemm_mi_kernel<<<(NCOLS / BM) * (NCOLS / BN), 256, GEMM_SMEM>>>();
    finalize_kernel<<<1, 256>>>(out);
}